// round 13
// baseline (speedup 1.0000x reference)
#include <cuda_runtime.h>
#include <cuda_bf16.h>

#define N_G    512
#define W_IMG  256
#define H_IMG  256
#define TLX    16                 // tile width (pixels)
#define TLY    8                  // tile height
#define NTX    (W_IMG / TLX)      // 16 tiles in x
#define NTY    (H_IMG / TLY)      // 32 tiles in y
#define NCHUNK 4
#define CHUNK  (N_G / NCHUNK)     // 128
#define LOG2E  1.4426950408889634f

// Sorted per-gaussian data (written by prep, read by render)
__device__ float4 d_cull[N_G]; // mx, my, rx2, ry2  (per-axis bbox half-extents^2)
__device__ float4 d_gA[N_G];   // mx, my, iaS, ibcS   (S = -0.5*log2e folded in)
__device__ float4 d_gB[N_G];   // idS, coef, pr(=coef*red), pg(=coef*green)
__device__ float  d_pb[N_G];   // coef*blue

// Per-chunk partials: (r, g, b, T) per pixel
__device__ float4 d_part[NCHUNK][H_IMG * W_IMG];

// Per-tile arrival counters (zero-init; self-reset each frame)
__device__ unsigned d_tile_cnt[NTX * NTY];

// ---------------------------------------------------------------------------
// Kernel 1: per-gaussian preprocessing + stable depth sort.
// 128 blocks x 128 threads (4 warps, 1 gaussian/warp, lane-distributed rank).
// ---------------------------------------------------------------------------
__global__ __launch_bounds__(128) void prep_kernel(const float* __restrict__ means,
                            const float* __restrict__ covs,
                            const float* __restrict__ colors,
                            const float* __restrict__ opac,
                            const float* __restrict__ Km,
                            const float* __restrict__ Rm,
                            const float* __restrict__ tv)
{
    __shared__ float sdepth[N_G];
    const int t    = threadIdx.x;          // 0..127
    const int warp = t >> 5;               // 0..3
    const int lane = t & 31;
    const int i    = blockIdx.x * 4 + warp;    // this warp's gaussian

    const float R00=Rm[0],R01=Rm[1],R02=Rm[2];
    const float R10=Rm[3],R11=Rm[4],R12=Rm[5];
    const float R20=Rm[6],R21=Rm[7],R22=Rm[8];
    const float t0=tv[0], t1=tv[1], t2=tv[2];

    // all 512 depths into shared (4 per thread)
#pragma unroll
    for (int k = 0; k < 4; k++) {
        const int j = k * 128 + t;
        const float m0 = means[3*j], m1 = means[3*j+1], m2 = means[3*j+2];
        const float Zj = R20*m0 + R21*m1 + R22*m2 + t2;
        sdepth[j] = fmaxf(Zj, 1.0f);
    }
    __syncthreads();

    // own camera-space position (all lanes redundantly)
    const float m0 = means[3*i], m1 = means[3*i+1], m2 = means[3*i+2];
    const float X = R00*m0 + R01*m1 + R02*m2 + t0;
    const float Y = R10*m0 + R11*m1 + R12*m2 + t1;
    const float Z = R20*m0 + R21*m1 + R22*m2 + t2;
    const float depth = fmaxf(Z, 1.0f);

    // stable rank, distributed over lanes: j = lane, lane+32, ...
    int cnt = 0;
#pragma unroll
    for (int k = 0; k < N_G / 32; k++) {
        const int j = k * 32 + lane;
        const float dj = sdepth[j];
        cnt += (dj < depth) || (dj == depth && j < i);
    }
    const int rank = __reduce_add_sync(0xffffffffu, cnt);

    // per-gaussian math (all lanes redundantly; lane 0 stores)
    const float K00=Km[0],K01=Km[1],K02=Km[2];
    const float K10=Km[3],K11=Km[4],K12=Km[5];
    const float K20=Km[6],K21=Km[7],K22=Km[8];
    const float sx = K00*X + K01*Y + K02*Z;
    const float sy = K10*X + K11*Y + K12*Z;
    const float sz = K20*X + K21*Y + K22*Z;
    const float rsz = __fdividef(1.0f, sz);
    const float mx2 = sx * rsz;
    const float my2 = sy * rsz;

    const float fx = K00, fy = K11;
    const float rZ  = __fdividef(1.0f, Z);
    const float j00 =  fx * rZ;
    const float j02 = -fx * X * rZ * rZ;
    const float j11 =  fy * rZ;
    const float j12 = -fy * Y * rZ * rZ;

    float C[3][3];
#pragma unroll
    for (int r = 0; r < 3; r++)
#pragma unroll
        for (int c = 0; c < 3; c++)
            C[r][c] = covs[9*i + 3*r + c];

    const float Rm3[3][3] = {{R00,R01,R02},{R10,R11,R12},{R20,R21,R22}};
    float M[3][3], CC[3][3];
#pragma unroll
    for (int r = 0; r < 3; r++)
#pragma unroll
        for (int c = 0; c < 3; c++)
            M[r][c] = Rm3[r][0]*C[0][c] + Rm3[r][1]*C[1][c] + Rm3[r][2]*C[2][c];
#pragma unroll
    for (int r = 0; r < 3; r++)
#pragma unroll
        for (int c = 0; c < 3; c++)
            CC[r][c] = M[r][0]*Rm3[c][0] + M[r][1]*Rm3[c][1] + M[r][2]*Rm3[c][2];

    float v0[3], v1[3];
#pragma unroll
    for (int k = 0; k < 3; k++) {
        v0[k] = CC[k][0]*j00 + CC[k][2]*j02;
        v1[k] = CC[k][1]*j11 + CC[k][2]*j12;
    }
    float a = j00*v0[0] + j02*v0[2];
    float c = j11*v0[1] + j12*v0[2];
    float b = j00*v1[0] + j02*v1[2];
    float d = j11*v1[1] + j12*v1[2];
    a += 1e-4f;
    d += 1e-4f;

    const float det  = a*d - b*c;
    const float rdet = __fdividef(1.0f, det);
    const float S    = -0.5f * LOG2E;            // fold into quad form: exp -> exp2
    const float iaS  = S * d * rdet;
    const float ibcS = S * (-b - c) * rdet;
    const float idS  = S * a * rdet;
    float rsq;                                    // rsqrt(det)
    asm("rsqrt.approx.f32 %0, %1;" : "=f"(rsq) : "f"(det));
    const float norm = (1.0f / (2.0f * 3.14159265358979323846f)) * rsq;

    const bool  valid = (depth > 1.0f) && (depth < 50.0f);
    const float coef  = valid ? opac[i] * norm : 0.0f;

    // per-axis conservative extents at alpha threshold 1e-6
    float rx2 = -1.0f, ry2 = -1.0f;
    if (coef > 0.0f) {
        const float L = __logf(coef * 1e6f);
        if (L > 0.0f) {
            rx2 = 2.0f * a * L;
            ry2 = 2.0f * d * L;
        }
    }

    if (lane == 0) {
        const float cr = colors[3*i + 0], cg = colors[3*i + 1], cb = colors[3*i + 2];
        d_cull[rank] = make_float4(mx2, my2, rx2, ry2);
        d_gA[rank]   = make_float4(mx2, my2, iaS, ibcS);
        d_gB[rank]   = make_float4(idS, coef, coef * cr, coef * cg);
        d_pb[rank]   = coef * cb;
    }

    asm volatile("griddepcontrol.launch_dependents;");
}

// ---------------------------------------------------------------------------
// Kernel 2: chunked tile render + in-kernel combine.
// Grid (NCHUNK, NTX*NTY) = (4, 512) = 2048 blocks of 128 threads; 16x8 tile,
// 1 pixel/thread. blockIdx.y is a center-out tile order index so heavy
// central tiles are scheduled first; chunks iterate innermost.
// Last block per tile combines the NCHUNK partials.
// ---------------------------------------------------------------------------
__global__ __launch_bounds__(128) void render_kernel(float* __restrict__ out)
{
    __shared__ float4 s0[CHUNK];   // mx, my, iaS, ibcS
    __shared__ float4 s1[CHUNK];   // idS, coef, pr, pg
    __shared__ float  s2[CHUNK];   // pb
    __shared__ int    s_wc[4];
    __shared__ unsigned s_old;

    const int tid = threadIdx.x;          // 0..127
    const int tx  = tid & 15;             // 0..15
    const int ty  = tid >> 4;             // 0..7

    // center-out tile remap: order idx -> tile coords
    const int o   = blockIdx.y;
    const int ox  = o & (NTX - 1);
    const int oy  = o >> 4;
    const int tx0 = (NTX/2) + ((ox & 1) ? -(ox/2 + 1) : ox/2);   // 8,7,9,6,...
    const int ty0 = (NTY/2) + ((oy & 1) ? -(oy/2 + 1) : oy/2);   // 16,15,17,...
    const int x0  = tx0 * TLX;
    const int y0  = ty0 * TLY;
    const int z   = blockIdx.x;
    const int gbase = z * CHUNK;

    const float fx0 = (float)x0,             fy0 = (float)y0;
    const float fx1 = (float)(x0 + TLX - 1), fy1 = (float)(y0 + TLY - 1);

    const int warp = tid >> 5;
    const int lane = tid & 31;

    asm volatile("griddepcontrol.wait;" ::: "memory");

    // cull + order-preserving compact (all 128 threads, one pass)
    {
        const int gi = gbase + tid;
        const float4 cu = d_cull[gi];
        const float dxm = fmaxf(0.0f, fmaxf(fx0 - cu.x, cu.x - fx1));
        const float dym = fmaxf(0.0f, fmaxf(fy0 - cu.y, cu.y - fy1));
        const bool ins  = (dxm*dxm <= cu.z) && (dym*dym <= cu.w); // neg => cull

        const unsigned bal = __ballot_sync(0xffffffffu, ins);
        if (lane == 0) s_wc[warp] = __popc(bal);
        __syncthreads();
        if (ins) {
            int off = 0;
            for (int w = 0; w < warp; w++) off += s_wc[w];
            const int pos = off + __popc(bal & ((1u << lane) - 1u));
            s0[pos] = d_gA[gi];
            s1[pos] = d_gB[gi];
            s2[pos] = d_pb[gi];
        }
    }
    __syncthreads();

    const int M = s_wc[0] + s_wc[1] + s_wc[2] + s_wc[3];
    const float px = (float)(x0 + tx);
    const float py = (float)(y0 + ty);

    float T = 1.0f, cr = 0.0f, cg = 0.0f, cb = 0.0f;
#pragma unroll 4
    for (int i = 0; i < M; i++) {
        const float4 g0 = s0[i];
        const float4 g1 = s1[i];
        const float  pb = s2[i];
        const float dx = px - g0.x;
        const float dy = py - g0.y;
        const float tq = fmaf(g0.w, dy, g0.z * dx);   // ibcS*dy + iaS*dx
        const float vq = g1.x * dy * dy;              // idS*dy^2
        const float q  = fmaf(tq, dx, vq);            // scaled exponent (log2)
        float e;
        asm("ex2.approx.f32 %0, %1;" : "=f"(e) : "f"(q));
        const float w = T * e;
        cr = fmaf(w, g1.z, cr);
        cg = fmaf(w, g1.w, cg);
        cb = fmaf(w, pb, cb);
        T  = fmaf(-w, g1.y, T);
    }

    const int pix = (y0 + ty) * W_IMG + (x0 + tx);
    d_part[z][pix] = make_float4(cr, cg, cb, T);
    __syncthreads();   // all partial stores issued (intra-block HB to tid 0)

    // release: tid 0's gpu-scope fence orders ALL block stores (via the
    // syncthreads happens-before) before its counter increment.
    const int tile_id = ty0 * NTX + tx0;
    if (tid == 0) {
        __threadfence();
        s_old = atomicAdd(&d_tile_cnt[tile_id], 1u);
    }
    __syncthreads();

    if (s_old == NCHUNK - 1) {
        // acquire: tid 0 observed the last arrival; its fence + syncthreads
        // makes all other blocks' partials visible to every thread here.
        if (tid == 0) __threadfence();
        __syncthreads();

        float r = 0.0f, g = 0.0f, b = 0.0f, Tt = 1.0f;
#pragma unroll
        for (int zz = 0; zz < NCHUNK; zz++) {
            float cx, cy, cz, cw;
            if (zz == z) { cx = cr; cy = cg; cz = cb; cw = T; }
            else {
                const float4 c = d_part[zz][pix];
                cx = c.x; cy = c.y; cz = c.z; cw = c.w;
            }
            r = fmaf(Tt, cx, r);
            g = fmaf(Tt, cy, g);
            b = fmaf(Tt, cz, b);
            Tt *= cw;
        }
        out[3*pix + 0] = r;
        out[3*pix + 1] = g;
        out[3*pix + 2] = b;

        if (tid == 0) d_tile_cnt[tile_id] = 0u;   // self-reset for next replay
    }
}

// ---------------------------------------------------------------------------
extern "C" void kernel_launch(void* const* d_in, const int* in_sizes, int n_in,
                              void* d_out, int out_size)
{
    const float* means  = (const float*)d_in[0];
    const float* covs   = (const float*)d_in[1];
    const float* colors = (const float*)d_in[2];
    const float* opac   = (const float*)d_in[3];
    const float* Km     = (const float*)d_in[4];
    const float* Rm     = (const float*)d_in[5];
    const float* tv     = (const float*)d_in[6];

    prep_kernel<<<128, 128>>>(means, covs, colors, opac, Km, Rm, tv);

    cudaLaunchConfig_t cfg = {};
    cfg.gridDim  = dim3(NCHUNK, NTX * NTY);
    cfg.blockDim = dim3(128);
    cudaLaunchAttribute attrs[1];
    attrs[0].id = cudaLaunchAttributeProgrammaticStreamSerialization;
    attrs[0].val.programmaticStreamSerializationAllowed = 1;
    cfg.attrs = attrs;
    cfg.numAttrs = 1;
    cudaLaunchKernelEx(&cfg, render_kernel, (float*)d_out);
}

// round 14
// speedup vs baseline: 1.2948x; 1.2948x over previous
#include <cuda_runtime.h>
#include <cuda_bf16.h>

#define N_G    512
#define W_IMG  256
#define H_IMG  256
#define TLX    16                 // tile width (pixels)
#define TLY    8                  // tile height
#define NCHUNK 4
#define CHUNK  (N_G / NCHUNK)     // 128
#define LOG2E  1.4426950408889634f

// Sorted per-gaussian data (written by prep, read by render)
__device__ float4 d_cull[N_G]; // mx, my, rx2, ry2  (per-axis bbox half-extents^2)
__device__ float4 d_gA[N_G];   // mx, my, iaS, ibcS   (S = -0.5*log2e folded in)
__device__ float4 d_gB[N_G];   // idS, lc(=log2 coef), r, g
__device__ float  d_pb[N_G];   // b

// Per-chunk partials: (r, g, b, T) per pixel
__device__ float4 d_part[NCHUNK][H_IMG * W_IMG];

// Per-tile arrival counters (zero-init; self-reset each frame)
__device__ unsigned d_tile_cnt[(W_IMG/TLX)*(H_IMG/TLY)];

// ---------------------------------------------------------------------------
// Kernel 1: per-gaussian preprocessing + stable depth sort.
// 128 blocks x 128 threads (4 warps, 1 gaussian/warp, lane-distributed rank).
// ---------------------------------------------------------------------------
__global__ __launch_bounds__(128) void prep_kernel(const float* __restrict__ means,
                            const float* __restrict__ covs,
                            const float* __restrict__ colors,
                            const float* __restrict__ opac,
                            const float* __restrict__ Km,
                            const float* __restrict__ Rm,
                            const float* __restrict__ tv)
{
    __shared__ float sdepth[N_G];
    const int t    = threadIdx.x;          // 0..127
    const int warp = t >> 5;               // 0..3
    const int lane = t & 31;
    const int i    = blockIdx.x * 4 + warp;    // this warp's gaussian

    const float R00=Rm[0],R01=Rm[1],R02=Rm[2];
    const float R10=Rm[3],R11=Rm[4],R12=Rm[5];
    const float R20=Rm[6],R21=Rm[7],R22=Rm[8];
    const float t0=tv[0], t1=tv[1], t2=tv[2];

    // all 512 depths into shared (4 per thread)
#pragma unroll
    for (int k = 0; k < 4; k++) {
        const int j = k * 128 + t;
        const float m0 = means[3*j], m1 = means[3*j+1], m2 = means[3*j+2];
        const float Zj = R20*m0 + R21*m1 + R22*m2 + t2;
        sdepth[j] = fmaxf(Zj, 1.0f);
    }
    __syncthreads();

    // own camera-space position (all lanes redundantly)
    const float m0 = means[3*i], m1 = means[3*i+1], m2 = means[3*i+2];
    const float X = R00*m0 + R01*m1 + R02*m2 + t0;
    const float Y = R10*m0 + R11*m1 + R12*m2 + t1;
    const float Z = R20*m0 + R21*m1 + R22*m2 + t2;
    const float depth = fmaxf(Z, 1.0f);

    // stable rank, distributed over lanes: j = lane, lane+32, ...
    int cnt = 0;
#pragma unroll
    for (int k = 0; k < N_G / 32; k++) {
        const int j = k * 32 + lane;
        const float dj = sdepth[j];
        cnt += (dj < depth) || (dj == depth && j < i);
    }
    const int rank = __reduce_add_sync(0xffffffffu, cnt);

    // per-gaussian math (all lanes redundantly; lane 0 stores)
    const float K00=Km[0],K01=Km[1],K02=Km[2];
    const float K10=Km[3],K11=Km[4],K12=Km[5];
    const float K20=Km[6],K21=Km[7],K22=Km[8];
    const float sx = K00*X + K01*Y + K02*Z;
    const float sy = K10*X + K11*Y + K12*Z;
    const float sz = K20*X + K21*Y + K22*Z;
    const float rsz = __fdividef(1.0f, sz);
    const float mx2 = sx * rsz;
    const float my2 = sy * rsz;

    const float fx = K00, fy = K11;
    const float rZ  = __fdividef(1.0f, Z);
    const float j00 =  fx * rZ;
    const float j02 = -fx * X * rZ * rZ;
    const float j11 =  fy * rZ;
    const float j12 = -fy * Y * rZ * rZ;

    float C[3][3];
#pragma unroll
    for (int r = 0; r < 3; r++)
#pragma unroll
        for (int c = 0; c < 3; c++)
            C[r][c] = covs[9*i + 3*r + c];

    const float Rm3[3][3] = {{R00,R01,R02},{R10,R11,R12},{R20,R21,R22}};
    float M[3][3], CC[3][3];
#pragma unroll
    for (int r = 0; r < 3; r++)
#pragma unroll
        for (int c = 0; c < 3; c++)
            M[r][c] = Rm3[r][0]*C[0][c] + Rm3[r][1]*C[1][c] + Rm3[r][2]*C[2][c];
#pragma unroll
    for (int r = 0; r < 3; r++)
#pragma unroll
        for (int c = 0; c < 3; c++)
            CC[r][c] = M[r][0]*Rm3[c][0] + M[r][1]*Rm3[c][1] + M[r][2]*Rm3[c][2];

    float v0[3], v1[3];
#pragma unroll
    for (int k = 0; k < 3; k++) {
        v0[k] = CC[k][0]*j00 + CC[k][2]*j02;
        v1[k] = CC[k][1]*j11 + CC[k][2]*j12;
    }
    float a = j00*v0[0] + j02*v0[2];
    float c = j11*v0[1] + j12*v0[2];
    float b = j00*v1[0] + j02*v1[2];
    float d = j11*v1[1] + j12*v1[2];
    a += 1e-4f;
    d += 1e-4f;

    const float det  = a*d - b*c;
    const float rdet = __fdividef(1.0f, det);
    const float S    = -0.5f * LOG2E;            // fold into quad form: exp -> exp2
    const float iaS  = S * d * rdet;
    const float ibcS = S * (-b - c) * rdet;
    const float idS  = S * a * rdet;
    float rsq;                                    // rsqrt(det)
    asm("rsqrt.approx.f32 %0, %1;" : "=f"(rsq) : "f"(det));
    const float norm = (1.0f / (2.0f * 3.14159265358979323846f)) * rsq;

    const bool  valid = (depth > 1.0f) && (depth < 50.0f);
    const float coef  = valid ? opac[i] * norm : 0.0f;

    // per-axis conservative extents at alpha threshold 1e-6
    float rx2 = -1.0f, ry2 = -1.0f;
    float lc  = -126.0f;                          // log2(coef); harmless default
    if (coef > 0.0f) {
        const float L = __logf(coef * 1e6f);      // ln(coef) + ln(1e6)
        if (L > 0.0f) {
            rx2 = 2.0f * a * L;
            ry2 = 2.0f * d * L;
        }
        lc = L * LOG2E - 19.9315686f;             // log2(coef) = L*log2e - log2(1e6)
    }

    if (lane == 0) {
        const float cr = colors[3*i + 0], cg = colors[3*i + 1], cb = colors[3*i + 2];
        d_cull[rank] = make_float4(mx2, my2, rx2, ry2);
        d_gA[rank]   = make_float4(mx2, my2, iaS, ibcS);
        d_gB[rank]   = make_float4(idS, lc, cr, cg);
        d_pb[rank]   = cb;
    }

    asm volatile("griddepcontrol.launch_dependents;");
}

// ---------------------------------------------------------------------------
// Kernel 2: chunked tile render + in-kernel combine.
// Grid (16,32,NCHUNK) = 2048 blocks of 128 threads; 16x8 tile, 1 px/thread.
// alpha = 2^(q + lc) comes straight from ex2 (coef folded into the exponent).
// Last block per tile combines the NCHUNK partials.
// ---------------------------------------------------------------------------
__global__ __launch_bounds__(128) void render_kernel(float* __restrict__ out)
{
    __shared__ float4 s0[CHUNK];   // mx, my, iaS, ibcS
    __shared__ float4 s1[CHUNK];   // idS, lc, r, g
    __shared__ float  s2[CHUNK];   // b
    __shared__ int    s_wc[4];
    __shared__ unsigned s_old;

    const int tid = threadIdx.x;          // 0..127
    const int tx  = tid & 15;             // 0..15
    const int ty  = tid >> 4;             // 0..7
    const int x0  = blockIdx.x * TLX;
    const int y0  = blockIdx.y * TLY;
    const int z   = blockIdx.z;
    const int gbase = z * CHUNK;

    const float fx0 = (float)x0,             fy0 = (float)y0;
    const float fx1 = (float)(x0 + TLX - 1), fy1 = (float)(y0 + TLY - 1);

    const int warp = tid >> 5;
    const int lane = tid & 31;

    asm volatile("griddepcontrol.wait;" ::: "memory");

    // cull + order-preserving compact (all 128 threads, one pass)
    {
        const int gi = gbase + tid;
        const float4 cu = d_cull[gi];
        const float dxm = fmaxf(0.0f, fmaxf(fx0 - cu.x, cu.x - fx1));
        const float dym = fmaxf(0.0f, fmaxf(fy0 - cu.y, cu.y - fy1));
        const bool ins  = (dxm*dxm <= cu.z) && (dym*dym <= cu.w); // neg => cull

        const unsigned bal = __ballot_sync(0xffffffffu, ins);
        if (lane == 0) s_wc[warp] = __popc(bal);
        __syncthreads();
        if (ins) {
            int off = 0;
            for (int w = 0; w < warp; w++) off += s_wc[w];
            const int pos = off + __popc(bal & ((1u << lane) - 1u));
            s0[pos] = d_gA[gi];
            s1[pos] = d_gB[gi];
            s2[pos] = d_pb[gi];
        }
    }
    __syncthreads();

    const int M = s_wc[0] + s_wc[1] + s_wc[2] + s_wc[3];
    const float px = (float)(x0 + tx);
    const float py = (float)(y0 + ty);

    float T = 1.0f, cr = 0.0f, cg = 0.0f, cb = 0.0f;
#pragma unroll 4
    for (int i = 0; i < M; i++) {
        const float4 g0 = s0[i];
        const float4 g1 = s1[i];
        const float  pb = s2[i];
        const float dx = px - g0.x;
        const float dy = py - g0.y;
        const float tq = fmaf(g0.w, dy, g0.z * dx);   // ibcS*dy + iaS*dx
        const float vq = fmaf(g1.x * dy, dy, g1.y);   // idS*dy^2 + log2(coef)
        const float q  = fmaf(tq, dx, vq);            // full scaled exponent
        float al;                                      // alpha = coef * gauss
        asm("ex2.approx.f32 %0, %1;" : "=f"(al) : "f"(q));
        const float w = T * al;
        cr = fmaf(w, g1.z, cr);
        cg = fmaf(w, g1.w, cg);
        cb = fmaf(w, pb, cb);
        T  = T - w;
    }

    const int pix = (y0 + ty) * W_IMG + (x0 + tx);
    d_part[z][pix] = make_float4(cr, cg, cb, T);
    __threadfence();
    __syncthreads();

    // last block of this tile combines the NCHUNK partials
    const int tile_id = blockIdx.y * (W_IMG/TLX) + blockIdx.x;
    if (tid == 0) s_old = atomicAdd(&d_tile_cnt[tile_id], 1u);
    __syncthreads();

    if (s_old == NCHUNK - 1) {
        __threadfence();   // acquire: other chunks' partials now visible

        float r = 0.0f, g = 0.0f, b = 0.0f, Tt = 1.0f;
#pragma unroll
        for (int zz = 0; zz < NCHUNK; zz++) {
            float cx, cy, cz, cw;
            if (zz == z) { cx = cr; cy = cg; cz = cb; cw = T; }
            else {
                const float4 c = d_part[zz][pix];
                cx = c.x; cy = c.y; cz = c.z; cw = c.w;
            }
            r = fmaf(Tt, cx, r);
            g = fmaf(Tt, cy, g);
            b = fmaf(Tt, cz, b);
            Tt *= cw;
        }
        out[3*pix + 0] = r;
        out[3*pix + 1] = g;
        out[3*pix + 2] = b;

        if (tid == 0) d_tile_cnt[tile_id] = 0u;   // self-reset for next replay
    }
}

// ---------------------------------------------------------------------------
extern "C" void kernel_launch(void* const* d_in, const int* in_sizes, int n_in,
                              void* d_out, int out_size)
{
    const float* means  = (const float*)d_in[0];
    const float* covs   = (const float*)d_in[1];
    const float* colors = (const float*)d_in[2];
    const float* opac   = (const float*)d_in[3];
    const float* Km     = (const float*)d_in[4];
    const float* Rm     = (const float*)d_in[5];
    const float* tv     = (const float*)d_in[6];

    prep_kernel<<<128, 128>>>(means, covs, colors, opac, Km, Rm, tv);

    cudaLaunchConfig_t cfg = {};
    cfg.gridDim  = dim3(W_IMG / TLX, H_IMG / TLY, NCHUNK);
    cfg.blockDim = dim3(128);
    cudaLaunchAttribute attrs[1];
    attrs[0].id = cudaLaunchAttributeProgrammaticStreamSerialization;
    attrs[0].val.programmaticStreamSerializationAllowed = 1;
    cfg.attrs = attrs;
    cfg.numAttrs = 1;
    cudaLaunchKernelEx(&cfg, render_kernel, (float*)d_out);
}

// round 16
// speedup vs baseline: 1.3653x; 1.0544x over previous
#include <cuda_runtime.h>
#include <cuda_bf16.h>

#define N_G    512
#define W_IMG  256
#define H_IMG  256
#define TLX    16                 // tile width (pixels)
#define TLY    8                  // tile height
#define NCHUNK 4
#define CHUNK  (N_G / NCHUNK)     // 128
#define LOG2E  1.4426950408889634f

// Sorted per-gaussian data (written by prep, read by render)
__device__ float4 d_cull[N_G]; // mx, my, rx2, ry2  (per-axis bbox half-extents^2)
__device__ float4 d_gA[N_G];   // mx, my, iaS, ibcS   (S = -0.5*log2e folded in)
__device__ float4 d_gB[N_G];   // idS, coef, pr(=coef*red), pg(=coef*green)
__device__ float  d_pb[N_G];   // coef*blue

// Per-chunk partials: (r, g, b, T) per pixel
__device__ float4 d_part[NCHUNK][H_IMG * W_IMG];

// Per-tile arrival counters (zero-init; self-reset each frame)
__device__ unsigned d_tile_cnt[(W_IMG/TLX)*(H_IMG/TLY)];

// ---------------------------------------------------------------------------
// Kernel 1: per-gaussian preprocessing + stable depth sort.
// 128 blocks x 128 threads (4 warps, 1 gaussian/warp, lane-distributed rank).
// ---------------------------------------------------------------------------
__global__ __launch_bounds__(128) void prep_kernel(const float* __restrict__ means,
                            const float* __restrict__ covs,
                            const float* __restrict__ colors,
                            const float* __restrict__ opac,
                            const float* __restrict__ Km,
                            const float* __restrict__ Rm,
                            const float* __restrict__ tv)
{
    __shared__ float sdepth[N_G];
    const int t    = threadIdx.x;          // 0..127
    const int warp = t >> 5;               // 0..3
    const int lane = t & 31;
    const int i    = blockIdx.x * 4 + warp;    // this warp's gaussian

    const float R00=Rm[0],R01=Rm[1],R02=Rm[2];
    const float R10=Rm[3],R11=Rm[4],R12=Rm[5];
    const float R20=Rm[6],R21=Rm[7],R22=Rm[8];
    const float t0=tv[0], t1=tv[1], t2=tv[2];

    // all 512 depths into shared (4 per thread)
#pragma unroll
    for (int k = 0; k < 4; k++) {
        const int j = k * 128 + t;
        const float m0 = means[3*j], m1 = means[3*j+1], m2 = means[3*j+2];
        const float Zj = R20*m0 + R21*m1 + R22*m2 + t2;
        sdepth[j] = fmaxf(Zj, 1.0f);
    }
    __syncthreads();

    // own camera-space position (all lanes redundantly)
    const float m0 = means[3*i], m1 = means[3*i+1], m2 = means[3*i+2];
    const float X = R00*m0 + R01*m1 + R02*m2 + t0;
    const float Y = R10*m0 + R11*m1 + R12*m2 + t1;
    const float Z = R20*m0 + R21*m1 + R22*m2 + t2;
    const float depth = fmaxf(Z, 1.0f);

    // stable rank, distributed over lanes: j = lane, lane+32, ...
    int cnt = 0;
#pragma unroll
    for (int k = 0; k < N_G / 32; k++) {
        const int j = k * 32 + lane;
        const float dj = sdepth[j];
        cnt += (dj < depth) || (dj == depth && j < i);
    }
    const int rank = __reduce_add_sync(0xffffffffu, cnt);

    // per-gaussian math (all lanes redundantly; lane 0 stores)
    const float K00=Km[0],K01=Km[1],K02=Km[2];
    const float K10=Km[3],K11=Km[4],K12=Km[5];
    const float K20=Km[6],K21=Km[7],K22=Km[8];
    const float sx = K00*X + K01*Y + K02*Z;
    const float sy = K10*X + K11*Y + K12*Z;
    const float sz = K20*X + K21*Y + K22*Z;
    const float rsz = __fdividef(1.0f, sz);
    const float mx2 = sx * rsz;
    const float my2 = sy * rsz;

    const float fx = K00, fy = K11;
    const float rZ  = __fdividef(1.0f, Z);
    const float j00 =  fx * rZ;
    const float j02 = -fx * X * rZ * rZ;
    const float j11 =  fy * rZ;
    const float j12 = -fy * Y * rZ * rZ;

    float C[3][3];
#pragma unroll
    for (int r = 0; r < 3; r++)
#pragma unroll
        for (int c = 0; c < 3; c++)
            C[r][c] = covs[9*i + 3*r + c];

    const float Rm3[3][3] = {{R00,R01,R02},{R10,R11,R12},{R20,R21,R22}};
    float M[3][3], CC[3][3];
#pragma unroll
    for (int r = 0; r < 3; r++)
#pragma unroll
        for (int c = 0; c < 3; c++)
            M[r][c] = Rm3[r][0]*C[0][c] + Rm3[r][1]*C[1][c] + Rm3[r][2]*C[2][c];
#pragma unroll
    for (int r = 0; r < 3; r++)
#pragma unroll
        for (int c = 0; c < 3; c++)
            CC[r][c] = M[r][0]*Rm3[c][0] + M[r][1]*Rm3[c][1] + M[r][2]*Rm3[c][2];

    float v0[3], v1[3];
#pragma unroll
    for (int k = 0; k < 3; k++) {
        v0[k] = CC[k][0]*j00 + CC[k][2]*j02;
        v1[k] = CC[k][1]*j11 + CC[k][2]*j12;
    }
    float a = j00*v0[0] + j02*v0[2];
    float c = j11*v0[1] + j12*v0[2];
    float b = j00*v1[0] + j02*v1[2];
    float d = j11*v1[1] + j12*v1[2];
    a += 1e-4f;
    d += 1e-4f;

    const float det  = a*d - b*c;
    const float rdet = __fdividef(1.0f, det);
    const float S    = -0.5f * LOG2E;            // fold into quad form: exp -> exp2
    const float iaS  = S * d * rdet;
    const float ibcS = S * (-b - c) * rdet;
    const float idS  = S * a * rdet;
    float rsq;                                    // rsqrt(det)
    asm("rsqrt.approx.f32 %0, %1;" : "=f"(rsq) : "f"(det));
    const float norm = (1.0f / (2.0f * 3.14159265358979323846f)) * rsq;

    const bool  valid = (depth > 1.0f) && (depth < 50.0f);
    const float coef  = valid ? opac[i] * norm : 0.0f;

    // per-axis conservative extents at alpha threshold 1e-6
    float rx2 = -1.0f, ry2 = -1.0f;
    if (coef > 0.0f) {
        const float L = __logf(coef * 1e6f);
        if (L > 0.0f) {
            rx2 = 2.0f * a * L;
            ry2 = 2.0f * d * L;
        }
    }

    if (lane == 0) {
        const float cr = colors[3*i + 0], cg = colors[3*i + 1], cb = colors[3*i + 2];
        d_cull[rank] = make_float4(mx2, my2, rx2, ry2);
        d_gA[rank]   = make_float4(mx2, my2, iaS, ibcS);
        d_gB[rank]   = make_float4(idS, coef, coef * cr, coef * cg);
        d_pb[rank]   = coef * cb;
    }

    asm volatile("griddepcontrol.launch_dependents;");
}

// ---------------------------------------------------------------------------
// Kernel 2: chunked tile render + in-kernel combine.
// Grid (16,32,NCHUNK) = 2048 blocks of 128 threads; 16x8 tile, 1 px/thread.
// Cull phase prefetches ALL gaussian data unconditionally (one memory round,
// MLP=4) and scatters survivors to smem after the ballot — removes the
// second dependent L2 round-trip from every block's critical path.
// Last block per tile combines the NCHUNK partials.
// ---------------------------------------------------------------------------
__global__ __launch_bounds__(128) void render_kernel(float* __restrict__ out)
{
    __shared__ float4 s0[CHUNK];   // mx, my, iaS, ibcS
    __shared__ float4 s1[CHUNK];   // idS, coef, pr, pg
    __shared__ float  s2[CHUNK];   // pb
    __shared__ int    s_wc[4];
    __shared__ unsigned s_old;

    const int tid = threadIdx.x;          // 0..127
    const int tx  = tid & 15;             // 0..15
    const int ty  = tid >> 4;             // 0..7
    const int x0  = blockIdx.x * TLX;
    const int y0  = blockIdx.y * TLY;
    const int z   = blockIdx.z;
    const int gbase = z * CHUNK;

    const float fx0 = (float)x0,             fy0 = (float)y0;
    const float fx1 = (float)(x0 + TLX - 1), fy1 = (float)(y0 + TLY - 1);

    const int warp = tid >> 5;
    const int lane = tid & 31;

    asm volatile("griddepcontrol.wait;" ::: "memory");

    // cull + order-preserving compact (all 128 threads, one pass).
    // All four loads issue back-to-back (MLP=4): one memory round.
    {
        const int gi = gbase + tid;
        const float4 cu = d_cull[gi];
        const float4 ga = d_gA[gi];       // prefetched unconditionally
        const float4 gb = d_gB[gi];
        const float  pb = d_pb[gi];

        const float dxm = fmaxf(0.0f, fmaxf(fx0 - cu.x, cu.x - fx1));
        const float dym = fmaxf(0.0f, fmaxf(fy0 - cu.y, cu.y - fy1));
        const bool ins  = (dxm*dxm <= cu.z) && (dym*dym <= cu.w); // neg => cull

        const unsigned bal = __ballot_sync(0xffffffffu, ins);
        if (lane == 0) s_wc[warp] = __popc(bal);
        __syncthreads();
        if (ins) {
            int off = 0;
            for (int w = 0; w < warp; w++) off += s_wc[w];
            const int pos = off + __popc(bal & ((1u << lane) - 1u));
            s0[pos] = ga;
            s1[pos] = gb;
            s2[pos] = pb;
        }
    }
    __syncthreads();

    const int M = s_wc[0] + s_wc[1] + s_wc[2] + s_wc[3];
    const float px = (float)(x0 + tx);
    const float py = (float)(y0 + ty);

    float T = 1.0f, cr = 0.0f, cg = 0.0f, cb = 0.0f;
#pragma unroll 4
    for (int i = 0; i < M; i++) {
        const float4 g0 = s0[i];
        const float4 g1 = s1[i];
        const float  pb = s2[i];
        const float dx = px - g0.x;
        const float dy = py - g0.y;
        const float tq = fmaf(g0.w, dy, g0.z * dx);   // ibcS*dy + iaS*dx
        const float vq = g1.x * dy * dy;              // idS*dy^2
        const float q  = fmaf(tq, dx, vq);            // scaled exponent (log2)
        float e;
        asm("ex2.approx.f32 %0, %1;" : "=f"(e) : "f"(q));
        const float w = T * e;
        cr = fmaf(w, g1.z, cr);
        cg = fmaf(w, g1.w, cg);
        cb = fmaf(w, pb, cb);
        T  = fmaf(-w, g1.y, T);
    }

    const int pix = (y0 + ty) * W_IMG + (x0 + tx);
    d_part[z][pix] = make_float4(cr, cg, cb, T);
    __threadfence();
    __syncthreads();

    // last block of this tile combines the NCHUNK partials
    const int tile_id = blockIdx.y * (W_IMG/TLX) + blockIdx.x;
    if (tid == 0) s_old = atomicAdd(&d_tile_cnt[tile_id], 1u);
    __syncthreads();

    if (s_old == NCHUNK - 1) {
        __threadfence();   // acquire: other chunks' partials now visible

        float r = 0.0f, g = 0.0f, b = 0.0f, Tt = 1.0f;
#pragma unroll
        for (int zz = 0; zz < NCHUNK; zz++) {
            float cx, cy, cz, cw;
            if (zz == z) { cx = cr; cy = cg; cz = cb; cw = T; }
            else {
                const float4 c = d_part[zz][pix];
                cx = c.x; cy = c.y; cz = c.z; cw = c.w;
            }
            r = fmaf(Tt, cx, r);
            g = fmaf(Tt, cy, g);
            b = fmaf(Tt, cz, b);
            Tt *= cw;
        }
        out[3*pix + 0] = r;
        out[3*pix + 1] = g;
        out[3*pix + 2] = b;

        if (tid == 0) d_tile_cnt[tile_id] = 0u;   // self-reset for next replay
    }
}

// ---------------------------------------------------------------------------
extern "C" void kernel_launch(void* const* d_in, const int* in_sizes, int n_in,
                              void* d_out, int out_size)
{
    const float* means  = (const float*)d_in[0];
    const float* covs   = (const float*)d_in[1];
    const float* colors = (const float*)d_in[2];
    const float* opac   = (const float*)d_in[3];
    const float* Km     = (const float*)d_in[4];
    const float* Rm     = (const float*)d_in[5];
    const float* tv     = (const float*)d_in[6];

    prep_kernel<<<128, 128>>>(means, covs, colors, opac, Km, Rm, tv);

    cudaLaunchConfig_t cfg = {};
    cfg.gridDim  = dim3(W_IMG / TLX, H_IMG / TLY, NCHUNK);
    cfg.blockDim = dim3(128);
    cudaLaunchAttribute attrs[1];
    attrs[0].id = cudaLaunchAttributeProgrammaticStreamSerialization;
    attrs[0].val.programmaticStreamSerializationAllowed = 1;
    cfg.attrs = attrs;
    cfg.numAttrs = 1;
    cudaLaunchKernelEx(&cfg, render_kernel, (float*)d_out);
}